// round 9
// baseline (speedup 1.0000x reference)
#include <cuda_runtime.h>
#include <cstddef>

#define Bdim 128
#define Sdim 512
#define Idim 256
#define Hdim 1024
#define NCTA 128
#define CHUNK 8

// Split-K partial buffer: 16 K-splits x [B][H] fp32 = 8 MB (static scratch, no allocs)
__device__ float g_P[16 * Bdim * Hdim];
__device__ unsigned g_count = 0;
__device__ unsigned g_gen = 0;

__device__ __forceinline__ unsigned ldv(const unsigned* p) {
    unsigned v;
    asm volatile("ld.volatile.global.u32 %0, [%1];" : "=r"(v) : "l"(p));
    return v;
}

__device__ __forceinline__ float4 ldcg4(const float* p) {
    return __ldcg(reinterpret_cast<const float4*>(p));
}

// Software grid barrier. Safe because grid (128 CTAs) <= #SMs (148) so all CTAs
// are co-resident in wave 1. gen is monotonically increasing -> graph replays
// keep working (count always returns to 0).
__device__ __forceinline__ void grid_barrier() {
    __threadfence();
    __syncthreads();
    if (threadIdx.x == 0) {
        unsigned my = ldv(&g_gen);
        if (atomicAdd(&g_count, 1u) == (unsigned)(NCTA - 1)) {
            atomicExch(&g_count, 0u);
            __threadfence();
            atomicAdd(&g_gen, 1u);
        } else {
            while (ldv(&g_gen) == my) { }
        }
    }
    __syncthreads();
}

// ---------------------------------------------------------------------------
// Phase 1: x_proj[s][b][h] = sum_i X[b][s][i] * W_ih[h][i] + b_ih[h] + b_hh[h]
// Written directly into the hs output region (scan overwrites in place).
// Tile 128(b) x 128(h), 256 threads, 8x8 micro, BK=8 double-buffered.
// ---------------------------------------------------------------------------
__global__ __launch_bounds__(256) void xproj_kernel(
    const float* __restrict__ X,
    const float* __restrict__ W_ih,
    const float* __restrict__ b_ih,
    const float* __restrict__ b_hh,
    float* __restrict__ hs)
{
    __shared__ float As[2][CHUNK][128];
    __shared__ float Bs[2][CHUNK][128];

    const int nb = blockIdx.x;   // 0..7  (column block of H)
    const int s  = blockIdx.y;   // 0..511
    const int tid = threadIdx.x;
    const int tx = tid & 15;
    const int ty = tid >> 4;
    const int lrow = tid >> 1;           // 0..127
    const int lk   = (tid & 1) * 4;      // 0 or 4

    const float* Abase = X + (size_t)s * Idim;                 // + b*(S*I) + i
    const float* Bbase = W_ih + (size_t)(nb * 128) * Idim;     // + n*I + i

    float acc[8][8];
    #pragma unroll
    for (int i = 0; i < 8; i++)
        #pragma unroll
        for (int j = 0; j < 8; j++) acc[i][j] = 0.0f;

    const int NCH = Idim / CHUNK;  // 32

    // prologue: load chunk 0
    {
        float4 av = *reinterpret_cast<const float4*>(Abase + (size_t)lrow * (Sdim * Idim) + lk);
        float4 bv = *reinterpret_cast<const float4*>(Bbase + (size_t)lrow * Idim + lk);
        As[0][lk + 0][lrow] = av.x; As[0][lk + 1][lrow] = av.y;
        As[0][lk + 2][lrow] = av.z; As[0][lk + 3][lrow] = av.w;
        Bs[0][lk + 0][lrow] = bv.x; Bs[0][lk + 1][lrow] = bv.y;
        Bs[0][lk + 2][lrow] = bv.z; Bs[0][lk + 3][lrow] = bv.w;
    }
    __syncthreads();

    int buf = 0;
    for (int c = 0; c < NCH; c++) {
        float4 an = make_float4(0.f, 0.f, 0.f, 0.f);
        float4 bn = make_float4(0.f, 0.f, 0.f, 0.f);
        if (c + 1 < NCH) {
            const int kc = (c + 1) * CHUNK;
            an = *reinterpret_cast<const float4*>(Abase + (size_t)lrow * (Sdim * Idim) + kc + lk);
            bn = *reinterpret_cast<const float4*>(Bbase + (size_t)lrow * Idim + kc + lk);
        }
        #pragma unroll
        for (int k = 0; k < CHUNK; k++) {
            float a[8], b[8];
            *reinterpret_cast<float4*>(&a[0]) = *reinterpret_cast<const float4*>(&As[buf][k][ty * 8]);
            *reinterpret_cast<float4*>(&a[4]) = *reinterpret_cast<const float4*>(&As[buf][k][ty * 8 + 4]);
            *reinterpret_cast<float4*>(&b[0]) = *reinterpret_cast<const float4*>(&Bs[buf][k][tx * 8]);
            *reinterpret_cast<float4*>(&b[4]) = *reinterpret_cast<const float4*>(&Bs[buf][k][tx * 8 + 4]);
            #pragma unroll
            for (int i = 0; i < 8; i++)
                #pragma unroll
                for (int j = 0; j < 8; j++)
                    acc[i][j] += a[i] * b[j];
        }
        if (c + 1 < NCH) {
            const int nbuf = buf ^ 1;
            As[nbuf][lk + 0][lrow] = an.x; As[nbuf][lk + 1][lrow] = an.y;
            As[nbuf][lk + 2][lrow] = an.z; As[nbuf][lk + 3][lrow] = an.w;
            Bs[nbuf][lk + 0][lrow] = bn.x; Bs[nbuf][lk + 1][lrow] = bn.y;
            Bs[nbuf][lk + 2][lrow] = bn.z; Bs[nbuf][lk + 3][lrow] = bn.w;
            __syncthreads();
            buf = nbuf;
        }
    }

    // epilogue: add biases, store to hs[s][b][col]
    const int col0 = nb * 128 + tx * 8;
    float bias[8];
    #pragma unroll
    for (int j = 0; j < 8; j++) bias[j] = b_ih[col0 + j] + b_hh[col0 + j];

    #pragma unroll
    for (int i = 0; i < 8; i++) {
        const int brow = ty * 8 + i;
        float* o = hs + ((size_t)s * Bdim + brow) * Hdim + col0;
        float4 v0 = make_float4(acc[i][0] + bias[0], acc[i][1] + bias[1],
                                acc[i][2] + bias[2], acc[i][3] + bias[3]);
        float4 v1 = make_float4(acc[i][4] + bias[4], acc[i][5] + bias[5],
                                acc[i][6] + bias[6], acc[i][7] + bias[7]);
        *reinterpret_cast<float4*>(o)     = v0;
        *reinterpret_cast<float4*>(o + 4) = v1;
    }
}

// ---------------------------------------------------------------------------
// Phase 2: persistent scan. 128 CTAs = 8 N-blocks x 16 K-splits.
// Per step: partial GEMM (128x128 tile, BK=64 slice) -> barrier ->
// reduce 16 partials + x_proj, tanh, write hs[t] (in place) -> barrier.
// Cross-CTA reused addresses are read with ld.global.cg (L1 is not coherent).
// ---------------------------------------------------------------------------
__global__ __launch_bounds__(256) void rnn_scan_kernel(
    const float* __restrict__ hidden,
    const float* __restrict__ W_hh,
    const float* __restrict__ W_fc,
    const float* __restrict__ b_fc,
    float* __restrict__ out,
    float* __restrict__ hs,
    float* __restrict__ ss,
    float* __restrict__ sf)
{
    __shared__ float As[2][CHUNK][128];
    __shared__ float Bs[2][CHUNK][128];

    const int cta = blockIdx.x;
    const int nb = cta >> 4;      // 0..7   N-block
    const int ks = cta & 15;      // 0..15  K-split
    const int tid = threadIdx.x;
    const int tx = tid & 15;
    const int ty = tid >> 4;
    const int lrow = tid >> 1;
    const int lk   = (tid & 1) * 4;
    const int k0 = ks * 64;

    const float* Bbase = W_hh + (size_t)(nb * 128) * Hdim + k0;
    const int NCH = 64 / CHUNK;  // 8

    for (int t = 0; t < Sdim; t++) {
        const float* Abase = (t == 0 ? hidden : hs + (size_t)(t - 1) * Bdim * Hdim) + k0;

        float acc[8][8];
        #pragma unroll
        for (int i = 0; i < 8; i++)
            #pragma unroll
            for (int j = 0; j < 8; j++) acc[i][j] = 0.0f;

        // prologue chunk 0 (A via .cg: written by other CTAs last step)
        {
            float4 av = ldcg4(Abase + (size_t)lrow * Hdim + lk);
            float4 bv = *reinterpret_cast<const float4*>(Bbase + (size_t)lrow * Hdim + lk);
            As[0][lk + 0][lrow] = av.x; As[0][lk + 1][lrow] = av.y;
            As[0][lk + 2][lrow] = av.z; As[0][lk + 3][lrow] = av.w;
            Bs[0][lk + 0][lrow] = bv.x; Bs[0][lk + 1][lrow] = bv.y;
            Bs[0][lk + 2][lrow] = bv.z; Bs[0][lk + 3][lrow] = bv.w;
        }
        __syncthreads();

        int buf = 0;
        for (int c = 0; c < NCH; c++) {
            float4 an = make_float4(0.f, 0.f, 0.f, 0.f);
            float4 bn = make_float4(0.f, 0.f, 0.f, 0.f);
            if (c + 1 < NCH) {
                const int kc = (c + 1) * CHUNK;
                an = ldcg4(Abase + (size_t)lrow * Hdim + kc + lk);
                bn = *reinterpret_cast<const float4*>(Bbase + (size_t)lrow * Hdim + kc + lk);
            }
            #pragma unroll
            for (int k = 0; k < CHUNK; k++) {
                float a[8], b[8];
                *reinterpret_cast<float4*>(&a[0]) = *reinterpret_cast<const float4*>(&As[buf][k][ty * 8]);
                *reinterpret_cast<float4*>(&a[4]) = *reinterpret_cast<const float4*>(&As[buf][k][ty * 8 + 4]);
                *reinterpret_cast<float4*>(&b[0]) = *reinterpret_cast<const float4*>(&Bs[buf][k][tx * 8]);
                *reinterpret_cast<float4*>(&b[4]) = *reinterpret_cast<const float4*>(&Bs[buf][k][tx * 8 + 4]);
                #pragma unroll
                for (int i = 0; i < 8; i++)
                    #pragma unroll
                    for (int j = 0; j < 8; j++)
                        acc[i][j] += a[i] * b[j];
            }
            if (c + 1 < NCH) {
                const int nbuf = buf ^ 1;
                As[nbuf][lk + 0][lrow] = an.x; As[nbuf][lk + 1][lrow] = an.y;
                As[nbuf][lk + 2][lrow] = an.z; As[nbuf][lk + 3][lrow] = an.w;
                Bs[nbuf][lk + 0][lrow] = bn.x; Bs[nbuf][lk + 1][lrow] = bn.y;
                Bs[nbuf][lk + 2][lrow] = bn.z; Bs[nbuf][lk + 3][lrow] = bn.w;
                __syncthreads();
                buf = nbuf;
            }
        }

        // write partials: P[ks][b][nb*128 + n]
        {
            float* Pb = g_P + (size_t)ks * Bdim * Hdim + nb * 128 + tx * 8;
            #pragma unroll
            for (int i = 0; i < 8; i++) {
                const int brow = ty * 8 + i;
                float* p = Pb + (size_t)brow * Hdim;
                *reinterpret_cast<float4*>(p)     = make_float4(acc[i][0], acc[i][1], acc[i][2], acc[i][3]);
                *reinterpret_cast<float4*>(p + 4) = make_float4(acc[i][4], acc[i][5], acc[i][6], acc[i][7]);
            }
        }

        grid_barrier();

        // reduction: CTA c owns batch row b=c; sum 16 partials + x_proj, tanh,
        // overwrite hs[t] in place.
        {
            const int off = cta * Hdim + tid * 4;  // flat [B][H] float index
            float* xp = hs + (size_t)t * Bdim * Hdim + off;
            float4 sum = *reinterpret_cast<const float4*>(xp);  // first touch in launch
            #pragma unroll
            for (int q = 0; q < 16; q++) {
                float4 p = ldcg4(g_P + (size_t)q * Bdim * Hdim + off);
                sum.x += p.x; sum.y += p.y; sum.z += p.z; sum.w += p.w;
            }
            float4 hv = make_float4(tanhf(sum.x), tanhf(sum.y), tanhf(sum.z), tanhf(sum.w));
            *reinterpret_cast<float4*>(xp) = hv;
        }

        grid_barrier();
    }

    // ---- tail: state_start, state_final, fc output ----
    const float* hfin = hs + (size_t)(Sdim - 1) * Bdim * Hdim;
    {
        const int off = cta * Hdim + tid * 4;
        *reinterpret_cast<float4*>(ss + off) = ldcg4(hs + off);
        *reinterpret_cast<float4*>(sf + off) = ldcg4(hfin + off);
    }
    if (cta < 16) {
        const int w = tid >> 5;      // 0..7
        const int lane = tid & 31;
        const int b = cta * 8 + w;   // 0..127
        float sum = 0.0f;
        #pragma unroll 8
        for (int h = lane; h < Hdim; h += 32)
            sum += __ldcg(hfin + (size_t)b * Hdim + h) * W_fc[h];
        #pragma unroll
        for (int o = 16; o > 0; o >>= 1)
            sum += __shfl_down_sync(0xffffffffu, sum, o);
        if (lane == 0) out[b] = sum + b_fc[0];
    }
}

extern "C" void kernel_launch(void* const* d_in, const int* in_sizes, int n_in,
                              void* d_out, int out_size) {
    (void)in_sizes; (void)n_in; (void)out_size;
    const float* X      = (const float*)d_in[0];
    const float* hidden = (const float*)d_in[1];
    const float* W_ih   = (const float*)d_in[2];
    const float* W_hh   = (const float*)d_in[3];
    const float* b_ih   = (const float*)d_in[4];
    const float* b_hh   = (const float*)d_in[5];
    const float* W_fc   = (const float*)d_in[6];
    const float* b_fc   = (const float*)d_in[7];

    float* out = (float*)d_out;                       // (B, 1)            : 128
    float* hs  = out + Bdim;                          // (S, B, H)         : 67108864
    float* ss  = hs + (size_t)Sdim * Bdim * Hdim;     // state_start (B,H) : 131072
    float* sf  = ss + (size_t)Bdim * Hdim;            // state_final (B,H) : 131072

    xproj_kernel<<<dim3(8, Sdim), 256>>>(X, W_ih, b_ih, b_hh, hs);
    rnn_scan_kernel<<<NCTA, 256>>>(hidden, W_hh, W_fc, b_fc, out, hs, ss, sf);
}

// round 11
// speedup vs baseline: 1.7623x; 1.7623x over previous
#include <cuda_runtime.h>
#include <cuda_bf16.h>
#include <cstdint>
#include <cstddef>

#define Bdim 128
#define Sdim 512
#define Idim 256
#define Hdim 1024
#define NCTA 128
#define CHUNK 8

// scan decomposition: 16 N-blocks x 8 K-splits = 128 CTAs
#define NN 16
#define NK 8
#define NBLK 64    // N columns per CTA
#define KBLK 128   // K slice per CTA

// padded smem rows: 136 bf16 = 272 B stride -> conflict-free ldmatrix
#define ASTRIDE 272
#define SM_AHI 0
#define SM_ALO (SM_AHI + 128 * ASTRIDE)   // 34816
#define SM_BHI (SM_ALO + 128 * ASTRIDE)   // 69632
#define SM_BLO (SM_BHI + 64 * ASTRIDE)    // 87040
#define SMEM_SZ (SM_BLO + 64 * ASTRIDE)   // 104448 B

__device__ float g_P[NK * Bdim * Hdim];           // split-K partials (4 MB)
__device__ __nv_bfloat16 g_hi[Bdim * Hdim];       // h (hi bf16)
__device__ __nv_bfloat16 g_lo[Bdim * Hdim];       // h (lo bf16)
__device__ unsigned g_count = 0;
__device__ unsigned g_gen = 0;

// ---------------------------------------------------------------------------
// helpers
// ---------------------------------------------------------------------------
__device__ __forceinline__ unsigned ldv(const unsigned* p) {
    unsigned v;
    asm volatile("ld.volatile.global.u32 %0, [%1];" : "=r"(v) : "l"(p));
    return v;
}
__device__ __forceinline__ float4 ldcg4(const float* p) {
    return __ldcg(reinterpret_cast<const float4*>(p));
}
__device__ __forceinline__ uint32_t smem_u32(const void* p) {
    uint32_t a;
    asm("{ .reg .u64 t; cvta.to.shared.u64 t, %1; cvt.u32.u64 %0, t; }" : "=r"(a) : "l"(p));
    return a;
}

#define LDSM4(r, addr) \
    asm volatile("ldmatrix.sync.aligned.m8n8.x4.shared.b16 {%0,%1,%2,%3}, [%4];" \
        : "=r"((r)[0]), "=r"((r)[1]), "=r"((r)[2]), "=r"((r)[3]) : "r"(addr))

#define MMA_BF16(d, a, b) \
    asm volatile("mma.sync.aligned.m16n8k16.row.col.f32.bf16.bf16.f32 " \
        "{%0,%1,%2,%3}, {%4,%5,%6,%7}, {%8,%9}, {%0,%1,%2,%3};" \
        : "+f"((d)[0]), "+f"((d)[1]), "+f"((d)[2]), "+f"((d)[3]) \
        : "r"((a)[0]), "r"((a)[1]), "r"((a)[2]), "r"((a)[3]), \
          "r"((b)[0]), "r"((b)[1]))

// Software grid barrier (128 CTAs <= 148 SMs -> co-resident).
__device__ __forceinline__ void grid_barrier() {
    __threadfence();
    __syncthreads();
    if (threadIdx.x == 0) {
        unsigned my = ldv(&g_gen);
        if (atomicAdd(&g_count, 1u) == (unsigned)(NCTA - 1)) {
            atomicExch(&g_count, 0u);
            __threadfence();
            atomicAdd(&g_gen, 1u);
        } else {
            while (ldv(&g_gen) == my) { }
        }
    }
    __syncthreads();
}

// ---------------------------------------------------------------------------
// Phase 1: x_proj (fp32 FFMA GEMM, unchanged — known good)
// ---------------------------------------------------------------------------
__global__ __launch_bounds__(256) void xproj_kernel(
    const float* __restrict__ X,
    const float* __restrict__ W_ih,
    const float* __restrict__ b_ih,
    const float* __restrict__ b_hh,
    float* __restrict__ hs)
{
    __shared__ float As[2][CHUNK][128];
    __shared__ float Bs[2][CHUNK][128];

    const int nb = blockIdx.x;
    const int s  = blockIdx.y;
    const int tid = threadIdx.x;
    const int tx = tid & 15;
    const int ty = tid >> 4;
    const int lrow = tid >> 1;
    const int lk   = (tid & 1) * 4;

    const float* Abase = X + (size_t)s * Idim;
    const float* Bbase = W_ih + (size_t)(nb * 128) * Idim;

    float acc[8][8];
    #pragma unroll
    for (int i = 0; i < 8; i++)
        #pragma unroll
        for (int j = 0; j < 8; j++) acc[i][j] = 0.0f;

    const int NCH = Idim / CHUNK;

    {
        float4 av = *reinterpret_cast<const float4*>(Abase + (size_t)lrow * (Sdim * Idim) + lk);
        float4 bv = *reinterpret_cast<const float4*>(Bbase + (size_t)lrow * Idim + lk);
        As[0][lk + 0][lrow] = av.x; As[0][lk + 1][lrow] = av.y;
        As[0][lk + 2][lrow] = av.z; As[0][lk + 3][lrow] = av.w;
        Bs[0][lk + 0][lrow] = bv.x; Bs[0][lk + 1][lrow] = bv.y;
        Bs[0][lk + 2][lrow] = bv.z; Bs[0][lk + 3][lrow] = bv.w;
    }
    __syncthreads();

    int buf = 0;
    for (int c = 0; c < NCH; c++) {
        float4 an = make_float4(0.f, 0.f, 0.f, 0.f);
        float4 bn = make_float4(0.f, 0.f, 0.f, 0.f);
        if (c + 1 < NCH) {
            const int kc = (c + 1) * CHUNK;
            an = *reinterpret_cast<const float4*>(Abase + (size_t)lrow * (Sdim * Idim) + kc + lk);
            bn = *reinterpret_cast<const float4*>(Bbase + (size_t)lrow * Idim + kc + lk);
        }
        #pragma unroll
        for (int k = 0; k < CHUNK; k++) {
            float a[8], b[8];
            *reinterpret_cast<float4*>(&a[0]) = *reinterpret_cast<const float4*>(&As[buf][k][ty * 8]);
            *reinterpret_cast<float4*>(&a[4]) = *reinterpret_cast<const float4*>(&As[buf][k][ty * 8 + 4]);
            *reinterpret_cast<float4*>(&b[0]) = *reinterpret_cast<const float4*>(&Bs[buf][k][tx * 8]);
            *reinterpret_cast<float4*>(&b[4]) = *reinterpret_cast<const float4*>(&Bs[buf][k][tx * 8 + 4]);
            #pragma unroll
            for (int i = 0; i < 8; i++)
                #pragma unroll
                for (int j = 0; j < 8; j++)
                    acc[i][j] += a[i] * b[j];
        }
        if (c + 1 < NCH) {
            const int nbuf = buf ^ 1;
            As[nbuf][lk + 0][lrow] = an.x; As[nbuf][lk + 1][lrow] = an.y;
            As[nbuf][lk + 2][lrow] = an.z; As[nbuf][lk + 3][lrow] = an.w;
            Bs[nbuf][lk + 0][lrow] = bn.x; Bs[nbuf][lk + 1][lrow] = bn.y;
            Bs[nbuf][lk + 2][lrow] = bn.z; Bs[nbuf][lk + 3][lrow] = bn.w;
            __syncthreads();
            buf = nbuf;
        }
    }

    const int col0 = nb * 128 + tx * 8;
    float bias[8];
    #pragma unroll
    for (int j = 0; j < 8; j++) bias[j] = b_ih[col0 + j] + b_hh[col0 + j];

    #pragma unroll
    for (int i = 0; i < 8; i++) {
        const int brow = ty * 8 + i;
        float* o = hs + ((size_t)s * Bdim + brow) * Hdim + col0;
        float4 v0 = make_float4(acc[i][0] + bias[0], acc[i][1] + bias[1],
                                acc[i][2] + bias[2], acc[i][3] + bias[3]);
        float4 v1 = make_float4(acc[i][4] + bias[4], acc[i][5] + bias[5],
                                acc[i][6] + bias[6], acc[i][7] + bias[7]);
        *reinterpret_cast<float4*>(o)     = v0;
        *reinterpret_cast<float4*>(o + 4) = v1;
    }
}

// ---------------------------------------------------------------------------
// Phase 2: persistent mma.sync scan. h in bf16 hi/lo 2-split; fp32 accum.
// Per step: A-slice -> padded smem -> ldmatrix + 192 HMMA/warp ->
// direct STG of partials from acc regs -> barrier -> 8-way reduce + tanh +
// re-split -> barrier.
// ---------------------------------------------------------------------------
__global__ __launch_bounds__(256, 1) void rnn_scan_kernel(
    const float* __restrict__ hidden,
    const float* __restrict__ W_hh,
    const float* __restrict__ W_fc,
    const float* __restrict__ b_fc,
    float* __restrict__ out,
    float* __restrict__ hs,
    float* __restrict__ ss,
    float* __restrict__ sf)
{
    extern __shared__ char smem[];
    const uint32_t sbase = smem_u32(smem);
    const int tid = threadIdx.x;
    const int wid = tid >> 5;
    const int lid = tid & 31;
    const int cta = blockIdx.x;
    const int nb  = cta >> 3;     // 0..15 N-block
    const int ks  = cta & 7;      // 0..7  K-split
    const int k0  = ks * KBLK;

    // One-time: load + split W_hh tile [NBLK x KBLK] into resident padded smem
    #pragma unroll 4
    for (int i = 0; i < 32; i++) {
        int e = tid + i * 256;           // 0..8191
        int n = e >> 7;                  // 0..63
        int k = e & 127;                 // 0..127
        float w = W_hh[(size_t)(nb * NBLK + n) * Hdim + k0 + k];
        __nv_bfloat16 hi = __float2bfloat16(w);
        __nv_bfloat16 lo = __float2bfloat16(w - __bfloat162float(hi));
        *reinterpret_cast<__nv_bfloat16*>(smem + SM_BHI + n * ASTRIDE + k * 2) = hi;
        *reinterpret_cast<__nv_bfloat16*>(smem + SM_BLO + n * ASTRIDE + k * 2) = lo;
    }

    // One-time: split h0 (this CTA owns batch row b = cta)
    for (int j = tid; j < Hdim; j += 256) {
        float x = hidden[(size_t)cta * Hdim + j];
        __nv_bfloat16 hi = __float2bfloat16(x);
        __nv_bfloat16 lo = __float2bfloat16(x - __bfloat162float(hi));
        g_hi[(size_t)cta * Hdim + j] = hi;
        g_lo[(size_t)cta * Hdim + j] = lo;
    }
    __syncthreads();
    grid_barrier();   // h0 published everywhere

    // warp layout: 4(m) x 2(n)
    const int wm = (wid & 3) * 32;   // 2 m-tiles of 16
    const int wn = (wid >> 2) * 32;  // 4 n-tiles of 8

    // lane-static ldmatrix base addresses
    // A: lanes 0-7: row m0+j,k0 | 8-15: m0+8+j,k0 | 16-23: m0+j,k0+8 | 24-31: m0+8+j,k0+8
    const uint32_t aRow = (uint32_t)(wm + (lid & 15));
    const uint32_t aCol = (uint32_t)((lid >> 4) * 8);
    const uint32_t aHiB = sbase + SM_AHI + aRow * ASTRIDE + aCol * 2;
    const uint32_t aLoB = aHiB + (SM_ALO - SM_AHI);
    // B: lanes 0-7: n0+j,k0 | 8-15: n0+j,k0+8 | 16-23: n0+8+j,k0 | 24-31: n0+8+j,k0+8
    const uint32_t bRow = (uint32_t)(wn + ((lid >> 4) << 3) + (lid & 7));
    const uint32_t bCol = (uint32_t)(((lid >> 3) & 1) * 8);
    const uint32_t bHiB = sbase + SM_BHI + bRow * ASTRIDE + bCol * 2;
    const uint32_t bLoB = bHiB + (SM_BLO - SM_BHI);

    for (int t = 0; t < Sdim; t++) {
        // ---- A slice [128 x 128] hi/lo -> padded smem ----
        #pragma unroll
        for (int i = 0; i < 8; i++) {
            int u = tid + i * 256;       // 0..2047 (uint4 units)
            int m  = u >> 4;             // 0..127
            int c8 = u & 15;             // col group of 8 bf16
            size_t g = (size_t)m * Hdim + k0 + c8 * 8;
            uint4 vh = __ldcg(reinterpret_cast<const uint4*>(g_hi + g));
            uint4 vl = __ldcg(reinterpret_cast<const uint4*>(g_lo + g));
            *reinterpret_cast<uint4*>(smem + SM_AHI + m * ASTRIDE + c8 * 16) = vh;
            *reinterpret_cast<uint4*>(smem + SM_ALO + m * ASTRIDE + c8 * 16) = vl;
        }
        __syncthreads();

        // ---- ldmatrix + mma ----
        float acc[2][4][4];
        #pragma unroll
        for (int mt = 0; mt < 2; mt++)
            #pragma unroll
            for (int nt = 0; nt < 4; nt++)
                #pragma unroll
                for (int r = 0; r < 4; r++) acc[mt][nt][r] = 0.0f;

        #pragma unroll
        for (int kt = 0; kt < 8; kt++) {
            const uint32_t ko = (uint32_t)(kt * 32);  // 16 bf16 = 32B per k-tile
            uint32_t ah[2][4], al[2][4], bh[2][4], bl[2][4];
            LDSM4(ah[0], aHiB + ko);
            LDSM4(ah[1], aHiB + 16 * ASTRIDE + ko);
            LDSM4(al[0], aLoB + ko);
            LDSM4(al[1], aLoB + 16 * ASTRIDE + ko);
            LDSM4(bh[0], bHiB + ko);
            LDSM4(bh[1], bHiB + 16 * ASTRIDE + ko);
            LDSM4(bl[0], bLoB + ko);
            LDSM4(bl[1], bLoB + 16 * ASTRIDE + ko);
            #pragma unroll
            for (int mt = 0; mt < 2; mt++) {
                #pragma unroll
                for (int np = 0; np < 2; np++) {
                    MMA_BF16(acc[mt][np * 2 + 0], ah[mt], bh[np] + 0);
                    MMA_BF16(acc[mt][np * 2 + 0], ah[mt], bl[np] + 0);
                    MMA_BF16(acc[mt][np * 2 + 0], al[mt], bh[np] + 0);
                    MMA_BF16(acc[mt][np * 2 + 1], ah[mt], bh[np] + 2);
                    MMA_BF16(acc[mt][np * 2 + 1], ah[mt], bl[np] + 2);
                    MMA_BF16(acc[mt][np * 2 + 1], al[mt], bh[np] + 2);
                }
            }
        }

        // ---- store partials directly from acc fragments ----
        // d0,d1 -> (row, col..col+1); d2,d3 -> (row+8, col..col+1)
        #pragma unroll
        for (int mt = 0; mt < 2; mt++) {
            #pragma unroll
            for (int nt = 0; nt < 4; nt++) {
                const int row = wm + mt * 16 + (lid >> 2);
                const int col = wn + nt * 8 + (lid & 3) * 2;
                float* p = g_P + ((size_t)ks * Bdim + row) * Hdim + nb * NBLK + col;
                *reinterpret_cast<float2*>(p) =
                    make_float2(acc[mt][nt][0], acc[mt][nt][1]);
                *reinterpret_cast<float2*>(p + 8 * Hdim) =
                    make_float2(acc[mt][nt][2], acc[mt][nt][3]);
            }
        }

        grid_barrier();

        // ---- reduce: batch row b = cta; sum 8 partials + x_proj, tanh, re-split ----
        {
            const size_t off = (size_t)cta * Hdim + tid * 4;
            float* xp = hs + (size_t)t * Bdim * Hdim + off;
            float4 sum = *reinterpret_cast<const float4*>(xp);
            #pragma unroll
            for (int q = 0; q < NK; q++) {
                float4 p = ldcg4(g_P + (size_t)q * Bdim * Hdim + off);
                sum.x += p.x; sum.y += p.y; sum.z += p.z; sum.w += p.w;
            }
            float4 hv = make_float4(tanhf(sum.x), tanhf(sum.y), tanhf(sum.z), tanhf(sum.w));
            *reinterpret_cast<float4*>(xp) = hv;

            __nv_bfloat16 h0 = __float2bfloat16(hv.x);
            __nv_bfloat16 h1 = __float2bfloat16(hv.y);
            __nv_bfloat16 h2 = __float2bfloat16(hv.z);
            __nv_bfloat16 h3 = __float2bfloat16(hv.w);
            __nv_bfloat16 l0 = __float2bfloat16(hv.x - __bfloat162float(h0));
            __nv_bfloat16 l1 = __float2bfloat16(hv.y - __bfloat162float(h1));
            __nv_bfloat16 l2 = __float2bfloat16(hv.z - __bfloat162float(h2));
            __nv_bfloat16 l3 = __float2bfloat16(hv.w - __bfloat162float(h3));
            uint2 uh, ul;
            uh.x = (uint32_t)__bfloat16_as_ushort(h0) | ((uint32_t)__bfloat16_as_ushort(h1) << 16);
            uh.y = (uint32_t)__bfloat16_as_ushort(h2) | ((uint32_t)__bfloat16_as_ushort(h3) << 16);
            ul.x = (uint32_t)__bfloat16_as_ushort(l0) | ((uint32_t)__bfloat16_as_ushort(l1) << 16);
            ul.y = (uint32_t)__bfloat16_as_ushort(l2) | ((uint32_t)__bfloat16_as_ushort(l3) << 16);
            *reinterpret_cast<uint2*>(g_hi + off) = uh;
            *reinterpret_cast<uint2*>(g_lo + off) = ul;
        }

        grid_barrier();
    }

    // ---- tail: state_start, state_final, fc output ----
    const float* hfin = hs + (size_t)(Sdim - 1) * Bdim * Hdim;
    {
        const size_t off = (size_t)cta * Hdim + tid * 4;
        *reinterpret_cast<float4*>(ss + off) = ldcg4(hs + off);
        *reinterpret_cast<float4*>(sf + off) = ldcg4(hfin + off);
    }
    if (cta < 16) {
        const int w = tid >> 5;
        const int lane = tid & 31;
        const int b = cta * 8 + w;
        float sum = 0.0f;
        #pragma unroll 8
        for (int h = lane; h < Hdim; h += 32)
            sum += __ldcg(hfin + (size_t)b * Hdim + h) * W_fc[h];
        #pragma unroll
        for (int o = 16; o > 0; o >>= 1)
            sum += __shfl_down_sync(0xffffffffu, sum, o);
        if (lane == 0) out[b] = sum + b_fc[0];
    }
}

extern "C" void kernel_launch(void* const* d_in, const int* in_sizes, int n_in,
                              void* d_out, int out_size) {
    (void)in_sizes; (void)n_in; (void)out_size;
    const float* X      = (const float*)d_in[0];
    const float* hidden = (const float*)d_in[1];
    const float* W_ih   = (const float*)d_in[2];
    const float* W_hh   = (const float*)d_in[3];
    const float* b_ih   = (const float*)d_in[4];
    const float* b_hh   = (const float*)d_in[5];
    const float* W_fc   = (const float*)d_in[6];
    const float* b_fc   = (const float*)d_in[7];

    float* out = (float*)d_out;                       // (B, 1)
    float* hs  = out + Bdim;                          // (S, B, H)
    float* ss  = hs + (size_t)Sdim * Bdim * Hdim;     // state_start (B,H)
    float* sf  = ss + (size_t)Bdim * Hdim;            // state_final (B,H)

    static bool attr_done = false;
    if (!attr_done) {
        cudaFuncSetAttribute(rnn_scan_kernel,
                             cudaFuncAttributeMaxDynamicSharedMemorySize, SMEM_SZ);
        attr_done = true;
    }

    xproj_kernel<<<dim3(8, Sdim), 256>>>(X, W_ih, b_ih, b_hh, hs);
    rnn_scan_kernel<<<NCTA, 256, SMEM_SZ>>>(hidden, W_hh, W_fc, b_fc, out, hs, ss, sf);
}

// round 12
// speedup vs baseline: 1.9992x; 1.1344x over previous
#include <cuda_runtime.h>
#include <cuda_bf16.h>
#include <cstdint>
#include <cstddef>

#define Bdim 128
#define Sdim 512
#define Idim 256
#define Hdim 1024
#define NCTA 128

// scan decomposition: 16 N-blocks x 8 K-splits = 128 CTAs
#define NK 8
#define NBLK 64    // N columns per CTA (scan)
#define KBLK 128   // K slice per CTA (scan)

// scan smem: padded rows, 272 B stride -> conflict-free ldmatrix
#define ASTRIDE 272
#define SM_AHI 0
#define SM_ALO (SM_AHI + 128 * ASTRIDE)
#define SM_BHI (SM_ALO + 128 * ASTRIDE)
#define SM_BLO (SM_BHI + 64 * ASTRIDE)
#define SMEM_SZ (SM_BLO + 64 * ASTRIDE)   // 104448 B

// xproj smem: K-chunk 64, padded 144 B stride
#define AST2 144
#define XA_HI 0
#define XA_LO (XA_HI + 128 * AST2)
#define XB_HI (XA_LO + 128 * AST2)
#define XB_LO (XB_HI + 128 * AST2)
#define XSMEM_SZ (XB_LO + 128 * AST2)     // 73728 B

__device__ float g_P[NK * Bdim * Hdim];           // split-K partials (4 MB)
__device__ __nv_bfloat16 g_hi[Bdim * Hdim];       // h (hi bf16)
__device__ __nv_bfloat16 g_lo[Bdim * Hdim];       // h (lo bf16)
__device__ unsigned g_grp[8 * 32];                // tree barrier: 8 groups, 128B apart
__device__ unsigned g_root = 0;
__device__ unsigned g_gen = 0;

// ---------------------------------------------------------------------------
// helpers
// ---------------------------------------------------------------------------
__device__ __forceinline__ unsigned ldv(const unsigned* p) {
    unsigned v;
    asm volatile("ld.volatile.global.u32 %0, [%1];" : "=r"(v) : "l"(p));
    return v;
}
__device__ __forceinline__ float4 ldcg4(const float* p) {
    return __ldcg(reinterpret_cast<const float4*>(p));
}
__device__ __forceinline__ uint32_t smem_u32(const void* p) {
    uint32_t a;
    asm("{ .reg .u64 t; cvta.to.shared.u64 t, %1; cvt.u32.u64 %0, t; }" : "=r"(a) : "l"(p));
    return a;
}

#define LDSM4(r, addr) \
    asm volatile("ldmatrix.sync.aligned.m8n8.x4.shared.b16 {%0,%1,%2,%3}, [%4];" \
        : "=r"((r)[0]), "=r"((r)[1]), "=r"((r)[2]), "=r"((r)[3]) : "r"(addr))

#define MMA_BF16(d, a, b) \
    asm volatile("mma.sync.aligned.m16n8k16.row.col.f32.bf16.bf16.f32 " \
        "{%0,%1,%2,%3}, {%4,%5,%6,%7}, {%8,%9}, {%0,%1,%2,%3};" \
        : "+f"((d)[0]), "+f"((d)[1]), "+f"((d)[2]), "+f"((d)[3]) \
        : "r"((a)[0]), "r"((a)[1]), "r"((a)[2]), "r"((a)[3]), \
          "r"((b)[0]), "r"((b)[1]))

// split a float4 into packed bf16 hi / lo pairs
__device__ __forceinline__ void split4(float4 v, uint2& uh, uint2& ul) {
    __nv_bfloat16 h0 = __float2bfloat16(v.x);
    __nv_bfloat16 h1 = __float2bfloat16(v.y);
    __nv_bfloat16 h2 = __float2bfloat16(v.z);
    __nv_bfloat16 h3 = __float2bfloat16(v.w);
    __nv_bfloat16 l0 = __float2bfloat16(v.x - __bfloat162float(h0));
    __nv_bfloat16 l1 = __float2bfloat16(v.y - __bfloat162float(h1));
    __nv_bfloat16 l2 = __float2bfloat16(v.z - __bfloat162float(h2));
    __nv_bfloat16 l3 = __float2bfloat16(v.w - __bfloat162float(h3));
    uh.x = (uint32_t)__bfloat16_as_ushort(h0) | ((uint32_t)__bfloat16_as_ushort(h1) << 16);
    uh.y = (uint32_t)__bfloat16_as_ushort(h2) | ((uint32_t)__bfloat16_as_ushort(h3) << 16);
    ul.x = (uint32_t)__bfloat16_as_ushort(l0) | ((uint32_t)__bfloat16_as_ushort(l1) << 16);
    ul.y = (uint32_t)__bfloat16_as_ushort(l2) | ((uint32_t)__bfloat16_as_ushort(l3) << 16);
}

// Two-level tree grid barrier (monotonic counters; 128 CTAs co-resident).
__device__ __forceinline__ void grid_barrier() {
    __threadfence();
    __syncthreads();
    if (threadIdx.x == 0) {
        unsigned my = ldv(&g_gen);
        unsigned o = atomicAdd(&g_grp[(blockIdx.x & 7) * 32], 1u);
        if ((o & 15u) == 15u) {
            unsigned r = atomicAdd(&g_root, 1u);
            if ((r & 7u) == 7u) atomicAdd(&g_gen, 1u);
        }
        while (ldv(&g_gen) == my) { }
    }
    __syncthreads();
}

// ---------------------------------------------------------------------------
// Phase 1: x_proj via bf16 hi/lo mma.sync.
// Block = (nb in 0..7, s in 0..511): M=128(b) x N=128(h-cols) x K=256,
// K chunked by 64 through smem. 8 warps in 4(m) x 2(n).
// ---------------------------------------------------------------------------
__global__ __launch_bounds__(256) void xproj_kernel(
    const float* __restrict__ X,
    const float* __restrict__ W_ih,
    const float* __restrict__ b_ih,
    const float* __restrict__ b_hh,
    float* __restrict__ hs)
{
    extern __shared__ char xsm[];
    const uint32_t sbase = smem_u32(xsm);
    const int nb = blockIdx.x;
    const int s  = blockIdx.y;
    const int tid = threadIdx.x;
    const int wid = tid >> 5;
    const int lid = tid & 31;

    const int wm = (wid & 3) * 32;   // 2 m-tiles of 16
    const int wn = (wid >> 2) * 64;  // 4 B LDSM groups of 16

    const uint32_t aRow = (uint32_t)(wm + (lid & 15));
    const uint32_t aCol = (uint32_t)((lid >> 4) * 8);
    const uint32_t aHiB = sbase + XA_HI + aRow * AST2 + aCol * 2;
    const uint32_t aLoB = aHiB + (XA_LO - XA_HI);
    const uint32_t bRow = (uint32_t)(wn + ((lid >> 4) << 3) + (lid & 7));
    const uint32_t bCol = (uint32_t)(((lid >> 3) & 1) * 8);
    const uint32_t bHiB = sbase + XB_HI + bRow * AST2 + bCol * 2;
    const uint32_t bLoB = bHiB + (XB_LO - XB_HI);

    float acc[2][8][4];
    #pragma unroll
    for (int mt = 0; mt < 2; mt++)
        #pragma unroll
        for (int nf = 0; nf < 8; nf++)
            #pragma unroll
            for (int r = 0; r < 4; r++) acc[mt][nf][r] = 0.0f;

    for (int c = 0; c < 4; c++) {
        const int kc = c * 64;
        // load + split A chunk: X[b][s][kc..kc+63], row b = 0..127
        #pragma unroll
        for (int i = 0; i < 8; i++) {
            int u = tid + i * 256;       // 0..2047
            int m  = u >> 4;             // 0..127
            int c4 = u & 15;             // float4 group
            float4 v = *reinterpret_cast<const float4*>(
                X + ((size_t)m * Sdim + s) * Idim + kc + c4 * 4);
            uint2 uh, ul;
            split4(v, uh, ul);
            *reinterpret_cast<uint2*>(xsm + XA_HI + m * AST2 + c4 * 8) = uh;
            *reinterpret_cast<uint2*>(xsm + XA_LO + m * AST2 + c4 * 8) = ul;
        }
        // load + split B chunk: W_ih[nb*128 + n][kc..kc+63]
        #pragma unroll
        for (int i = 0; i < 8; i++) {
            int u = tid + i * 256;
            int n  = u >> 4;
            int c4 = u & 15;
            float4 v = *reinterpret_cast<const float4*>(
                W_ih + (size_t)(nb * 128 + n) * Idim + kc + c4 * 4);
            uint2 uh, ul;
            split4(v, uh, ul);
            *reinterpret_cast<uint2*>(xsm + XB_HI + n * AST2 + c4 * 8) = uh;
            *reinterpret_cast<uint2*>(xsm + XB_LO + n * AST2 + c4 * 8) = ul;
        }
        __syncthreads();

        #pragma unroll
        for (int kt = 0; kt < 4; kt++) {
            const uint32_t ko = (uint32_t)(kt * 32);
            uint32_t ah[2][4], al[2][4];
            LDSM4(ah[0], aHiB + ko);
            LDSM4(ah[1], aHiB + 16 * AST2 + ko);
            LDSM4(al[0], aLoB + ko);
            LDSM4(al[1], aLoB + 16 * AST2 + ko);
            #pragma unroll
            for (int np = 0; np < 4; np++) {
                uint32_t bh[4], bl[4];
                LDSM4(bh, bHiB + np * (16 * AST2) + ko);
                LDSM4(bl, bLoB + np * (16 * AST2) + ko);
                #pragma unroll
                for (int mt = 0; mt < 2; mt++) {
                    MMA_BF16(acc[mt][np * 2 + 0], ah[mt], bh + 0);
                    MMA_BF16(acc[mt][np * 2 + 0], ah[mt], bl + 0);
                    MMA_BF16(acc[mt][np * 2 + 0], al[mt], bh + 0);
                    MMA_BF16(acc[mt][np * 2 + 1], ah[mt], bh + 2);
                    MMA_BF16(acc[mt][np * 2 + 1], ah[mt], bl + 2);
                    MMA_BF16(acc[mt][np * 2 + 1], al[mt], bh + 2);
                }
            }
        }
        __syncthreads();
    }

    // epilogue: add bias, store fragments to hs[s][b][col]
    #pragma unroll
    for (int mt = 0; mt < 2; mt++) {
        const int row = wm + mt * 16 + (lid >> 2);
        #pragma unroll
        for (int nf = 0; nf < 8; nf++) {
            const int col = nb * 128 + wn + nf * 8 + (lid & 3) * 2;
            const float bb0 = __ldg(b_ih + col) + __ldg(b_hh + col);
            const float bb1 = __ldg(b_ih + col + 1) + __ldg(b_hh + col + 1);
            float* o = hs + ((size_t)s * Bdim + row) * Hdim + col;
            *reinterpret_cast<float2*>(o) =
                make_float2(acc[mt][nf][0] + bb0, acc[mt][nf][1] + bb1);
            *reinterpret_cast<float2*>(o + 8 * Hdim) =
                make_float2(acc[mt][nf][2] + bb0, acc[mt][nf][3] + bb1);
        }
    }
}

// ---------------------------------------------------------------------------
// Phase 2: persistent mma.sync scan (unchanged math, tree barrier).
// ---------------------------------------------------------------------------
__global__ __launch_bounds__(256, 1) void rnn_scan_kernel(
    const float* __restrict__ hidden,
    const float* __restrict__ W_hh,
    const float* __restrict__ W_fc,
    const float* __restrict__ b_fc,
    float* __restrict__ out,
    float* __restrict__ hs,
    float* __restrict__ ss,
    float* __restrict__ sf)
{
    extern __shared__ char smem[];
    const uint32_t sbase = smem_u32(smem);
    const int tid = threadIdx.x;
    const int wid = tid >> 5;
    const int lid = tid & 31;
    const int cta = blockIdx.x;
    const int nb  = cta >> 3;     // 0..15 N-block
    const int ks  = cta & 7;      // 0..7  K-split
    const int k0  = ks * KBLK;

    // One-time: load + split W_hh tile [NBLK x KBLK] into resident padded smem
    #pragma unroll 4
    for (int i = 0; i < 32; i++) {
        int e = tid + i * 256;
        int n = e >> 7;
        int k = e & 127;
        float w = W_hh[(size_t)(nb * NBLK + n) * Hdim + k0 + k];
        __nv_bfloat16 hi = __float2bfloat16(w);
        __nv_bfloat16 lo = __float2bfloat16(w - __bfloat162float(hi));
        *reinterpret_cast<__nv_bfloat16*>(smem + SM_BHI + n * ASTRIDE + k * 2) = hi;
        *reinterpret_cast<__nv_bfloat16*>(smem + SM_BLO + n * ASTRIDE + k * 2) = lo;
    }

    // One-time: split h0 (this CTA owns batch row b = cta)
    for (int j = tid * 4; j < Hdim; j += 1024) {
        float4 v = *reinterpret_cast<const float4*>(hidden + (size_t)cta * Hdim + j);
        uint2 uh, ul;
        split4(v, uh, ul);
        *reinterpret_cast<uint2*>(g_hi + (size_t)cta * Hdim + j) = uh;
        *reinterpret_cast<uint2*>(g_lo + (size_t)cta * Hdim + j) = ul;
    }
    __syncthreads();
    grid_barrier();   // h0 published everywhere

    // warp layout: 4(m) x 2(n)
    const int wm = (wid & 3) * 32;
    const int wn = (wid >> 2) * 32;

    const uint32_t aRow = (uint32_t)(wm + (lid & 15));
    const uint32_t aCol = (uint32_t)((lid >> 4) * 8);
    const uint32_t aHiB = sbase + SM_AHI + aRow * ASTRIDE + aCol * 2;
    const uint32_t aLoB = aHiB + (SM_ALO - SM_AHI);
    const uint32_t bRow = (uint32_t)(wn + ((lid >> 4) << 3) + (lid & 7));
    const uint32_t bCol = (uint32_t)(((lid >> 3) & 1) * 8);
    const uint32_t bHiB = sbase + SM_BHI + bRow * ASTRIDE + bCol * 2;
    const uint32_t bLoB = bHiB + (SM_BLO - SM_BHI);

    for (int t = 0; t < Sdim; t++) {
        // ---- A slice [128 x 128] hi/lo -> padded smem ----
        #pragma unroll
        for (int i = 0; i < 8; i++) {
            int u = tid + i * 256;
            int m  = u >> 4;
            int c8 = u & 15;
            size_t g = (size_t)m * Hdim + k0 + c8 * 8;
            uint4 vh = __ldcg(reinterpret_cast<const uint4*>(g_hi + g));
            uint4 vl = __ldcg(reinterpret_cast<const uint4*>(g_lo + g));
            *reinterpret_cast<uint4*>(smem + SM_AHI + m * ASTRIDE + c8 * 16) = vh;
            *reinterpret_cast<uint4*>(smem + SM_ALO + m * ASTRIDE + c8 * 16) = vl;
        }
        __syncthreads();

        // ---- ldmatrix + mma ----
        float acc[2][4][4];
        #pragma unroll
        for (int mt = 0; mt < 2; mt++)
            #pragma unroll
            for (int nt = 0; nt < 4; nt++)
                #pragma unroll
                for (int r = 0; r < 4; r++) acc[mt][nt][r] = 0.0f;

        #pragma unroll
        for (int kt = 0; kt < 8; kt++) {
            const uint32_t ko = (uint32_t)(kt * 32);
            uint32_t ah[2][4], al[2][4], bh[2][4], bl[2][4];
            LDSM4(ah[0], aHiB + ko);
            LDSM4(ah[1], aHiB + 16 * ASTRIDE + ko);
            LDSM4(al[0], aLoB + ko);
            LDSM4(al[1], aLoB + 16 * ASTRIDE + ko);
            LDSM4(bh[0], bHiB + ko);
            LDSM4(bh[1], bHiB + 16 * ASTRIDE + ko);
            LDSM4(bl[0], bLoB + ko);
            LDSM4(bl[1], bLoB + 16 * ASTRIDE + ko);
            #pragma unroll
            for (int mt = 0; mt < 2; mt++) {
                #pragma unroll
                for (int np = 0; np < 2; np++) {
                    MMA_BF16(acc[mt][np * 2 + 0], ah[mt], bh[np] + 0);
                    MMA_BF16(acc[mt][np * 2 + 0], ah[mt], bl[np] + 0);
                    MMA_BF16(acc[mt][np * 2 + 0], al[mt], bh[np] + 0);
                    MMA_BF16(acc[mt][np * 2 + 1], ah[mt], bh[np] + 2);
                    MMA_BF16(acc[mt][np * 2 + 1], ah[mt], bl[np] + 2);
                    MMA_BF16(acc[mt][np * 2 + 1], al[mt], bh[np] + 2);
                }
            }
        }

        // ---- store partials directly from acc fragments ----
        #pragma unroll
        for (int mt = 0; mt < 2; mt++) {
            #pragma unroll
            for (int nt = 0; nt < 4; nt++) {
                const int row = wm + mt * 16 + (lid >> 2);
                const int col = wn + nt * 8 + (lid & 3) * 2;
                float* p = g_P + ((size_t)ks * Bdim + row) * Hdim + nb * NBLK + col;
                *reinterpret_cast<float2*>(p) =
                    make_float2(acc[mt][nt][0], acc[mt][nt][1]);
                *reinterpret_cast<float2*>(p + 8 * Hdim) =
                    make_float2(acc[mt][nt][2], acc[mt][nt][3]);
            }
        }

        grid_barrier();

        // ---- reduce: batch row b = cta; sum 8 partials + x_proj, tanh, re-split ----
        {
            const size_t off = (size_t)cta * Hdim + tid * 4;
            float* xp = hs + (size_t)t * Bdim * Hdim + off;
            float4 sum = *reinterpret_cast<const float4*>(xp);
            #pragma unroll
            for (int q = 0; q < NK; q++) {
                float4 p = ldcg4(g_P + (size_t)q * Bdim * Hdim + off);
                sum.x += p.x; sum.y += p.y; sum.z += p.z; sum.w += p.w;
            }
            float4 hv = make_float4(tanhf(sum.x), tanhf(sum.y), tanhf(sum.z), tanhf(sum.w));
            *reinterpret_cast<float4*>(xp) = hv;

            uint2 uh, ul;
            split4(hv, uh, ul);
            *reinterpret_cast<uint2*>(g_hi + off) = uh;
            *reinterpret_cast<uint2*>(g_lo + off) = ul;
        }

        grid_barrier();
    }

    // ---- tail: state_start, state_final, fc output ----
    const float* hfin = hs + (size_t)(Sdim - 1) * Bdim * Hdim;
    {
        const size_t off = (size_t)cta * Hdim + tid * 4;
        *reinterpret_cast<float4*>(ss + off) = ldcg4(hs + off);
        *reinterpret_cast<float4*>(sf + off) = ldcg4(hfin + off);
    }
    if (cta < 16) {
        const int w = tid >> 5;
        const int lane = tid & 31;
        const int b = cta * 8 + w;
        float sum = 0.0f;
        #pragma unroll 8
        for (int h = lane; h < Hdim; h += 32)
            sum += __ldcg(hfin + (size_t)b * Hdim + h) * W_fc[h];
        #pragma unroll
        for (int o = 16; o > 0; o >>= 1)
            sum += __shfl_down_sync(0xffffffffu, sum, o);
        if (lane == 0) out[b] = sum + b_fc[0];
    }
}

extern "C" void kernel_launch(void* const* d_in, const int* in_sizes, int n_in,
                              void* d_out, int out_size) {
    (void)in_sizes; (void)n_in; (void)out_size;
    const float* X      = (const float*)d_in[0];
    const float* hidden = (const float*)d_in[1];
    const float* W_ih   = (const float*)d_in[2];
    const float* W_hh   = (const float*)d_in[3];
    const float* b_ih   = (const float*)d_in[4];
    const float* b_hh   = (const float*)d_in[5];
    const float* W_fc   = (const float*)d_in[6];
    const float* b_fc   = (const float*)d_in[7];

    float* out = (float*)d_out;                       // (B, 1)
    float* hs  = out + Bdim;                          // (S, B, H)
    float* ss  = hs + (size_t)Sdim * Bdim * Hdim;     // state_start (B,H)
    float* sf  = ss + (size_t)Bdim * Hdim;            // state_final (B,H)

    cudaFuncSetAttribute(xproj_kernel,
                         cudaFuncAttributeMaxDynamicSharedMemorySize, XSMEM_SZ);
    cudaFuncSetAttribute(rnn_scan_kernel,
                         cudaFuncAttributeMaxDynamicSharedMemorySize, SMEM_SZ);

    xproj_kernel<<<dim3(8, Sdim), 256, XSMEM_SZ>>>(X, W_ih, b_ih, b_hh, hs);
    rnn_scan_kernel<<<NCTA, 256, SMEM_SZ>>>(hidden, W_hh, W_fc, b_fc, out, hs, ss, sf);
}

// round 13
// speedup vs baseline: 2.0171x; 1.0090x over previous
#include <cuda_runtime.h>
#include <cuda_bf16.h>
#include <cstdint>
#include <cstddef>

#define Bdim 128
#define Sdim 512
#define Idim 256
#define Hdim 1024
#define NCTA 128

// scan decomposition: 16 N-blocks x 8 K-splits = 128 CTAs
#define NK 8
#define NBLK 64    // N columns per CTA (scan)
#define KBLK 128   // K slice per CTA (scan)

// scan smem: padded rows, 272 B stride -> conflict-free ldmatrix
#define ASTRIDE 272
#define SM_AHI 0
#define SM_ALO (SM_AHI + 128 * ASTRIDE)
#define SM_BHI (SM_ALO + 128 * ASTRIDE)
#define SM_BLO (SM_BHI + 64 * ASTRIDE)
#define SMEM_SZ (SM_BLO + 64 * ASTRIDE)   // 104448 B

// xproj smem: K-chunk 64, padded 144 B stride
#define AST2 144
#define XA_HI 0
#define XA_LO (XA_HI + 128 * AST2)
#define XB_HI (XA_LO + 128 * AST2)
#define XB_LO (XB_HI + 128 * AST2)
#define XSMEM_SZ (XB_LO + 128 * AST2)     // 73728 B

__device__ float g_P[2 * NK * Bdim * Hdim];       // double-buffered split-K partials (8 MB)
__device__ __nv_bfloat16 g_Ahi[NK * Bdim * KBLK]; // per-group staged A tiles (hi)
__device__ __nv_bfloat16 g_Alo[NK * Bdim * KBLK]; // per-group staged A tiles (lo)
__device__ unsigned g_grp[8 * 32];                // global barrier tree: 8 groups
__device__ unsigned g_root = 0;
__device__ unsigned g_gen = 0;
__device__ unsigned g_gcnt[8 * 32];               // group barriers (per ks)
__device__ unsigned g_ggen[8 * 32];

// ---------------------------------------------------------------------------
// helpers
// ---------------------------------------------------------------------------
__device__ __forceinline__ unsigned ldv(const unsigned* p) {
    unsigned v;
    asm volatile("ld.volatile.global.u32 %0, [%1];" : "=r"(v) : "l"(p));
    return v;
}
__device__ __forceinline__ float2 ldcg2(const float* p) {
    return __ldcg(reinterpret_cast<const float2*>(p));
}
__device__ __forceinline__ float4 ldcg4(const float* p) {
    return __ldcg(reinterpret_cast<const float4*>(p));
}
__device__ __forceinline__ uint32_t smem_u32(const void* p) {
    uint32_t a;
    asm("{ .reg .u64 t; cvta.to.shared.u64 t, %1; cvt.u32.u64 %0, t; }" : "=r"(a) : "l"(p));
    return a;
}

#define LDSM4(r, addr) \
    asm volatile("ldmatrix.sync.aligned.m8n8.x4.shared.b16 {%0,%1,%2,%3}, [%4];" \
        : "=r"((r)[0]), "=r"((r)[1]), "=r"((r)[2]), "=r"((r)[3]) : "r"(addr))

#define MMA_BF16(d, a, b) \
    asm volatile("mma.sync.aligned.m16n8k16.row.col.f32.bf16.bf16.f32 " \
        "{%0,%1,%2,%3}, {%4,%5,%6,%7}, {%8,%9}, {%0,%1,%2,%3};" \
        : "+f"((d)[0]), "+f"((d)[1]), "+f"((d)[2]), "+f"((d)[3]) \
        : "r"((a)[0]), "r"((a)[1]), "r"((a)[2]), "r"((a)[3]), \
          "r"((b)[0]), "r"((b)[1]))

__device__ __forceinline__ void split4(float4 v, uint2& uh, uint2& ul) {
    __nv_bfloat16 h0 = __float2bfloat16(v.x);
    __nv_bfloat16 h1 = __float2bfloat16(v.y);
    __nv_bfloat16 h2 = __float2bfloat16(v.z);
    __nv_bfloat16 h3 = __float2bfloat16(v.w);
    __nv_bfloat16 l0 = __float2bfloat16(v.x - __bfloat162float(h0));
    __nv_bfloat16 l1 = __float2bfloat16(v.y - __bfloat162float(h1));
    __nv_bfloat16 l2 = __float2bfloat16(v.z - __bfloat162float(h2));
    __nv_bfloat16 l3 = __float2bfloat16(v.w - __bfloat162float(h3));
    uh.x = (uint32_t)__bfloat16_as_ushort(h0) | ((uint32_t)__bfloat16_as_ushort(h1) << 16);
    uh.y = (uint32_t)__bfloat16_as_ushort(h2) | ((uint32_t)__bfloat16_as_ushort(h3) << 16);
    ul.x = (uint32_t)__bfloat16_as_ushort(l0) | ((uint32_t)__bfloat16_as_ushort(l1) << 16);
    ul.y = (uint32_t)__bfloat16_as_ushort(l2) | ((uint32_t)__bfloat16_as_ushort(l3) << 16);
}
__device__ __forceinline__ void split2(float2 v, uint32_t& uh, uint32_t& ul) {
    __nv_bfloat16 h0 = __float2bfloat16(v.x);
    __nv_bfloat16 h1 = __float2bfloat16(v.y);
    __nv_bfloat16 l0 = __float2bfloat16(v.x - __bfloat162float(h0));
    __nv_bfloat16 l1 = __float2bfloat16(v.y - __bfloat162float(h1));
    uh = (uint32_t)__bfloat16_as_ushort(h0) | ((uint32_t)__bfloat16_as_ushort(h1) << 16);
    ul = (uint32_t)__bfloat16_as_ushort(l0) | ((uint32_t)__bfloat16_as_ushort(l1) << 16);
}

__device__ __forceinline__ float tanh_fast(float x) {
    float xc = fminf(fmaxf(x, -9.0f), 9.0f);
    float e = __expf(2.0f * xc);
    return __fdividef(e - 1.0f, e + 1.0f);
}

// Full-grid two-level tree barrier (128 CTAs co-resident).
__device__ __forceinline__ void grid_barrier() {
    __threadfence();
    __syncthreads();
    if (threadIdx.x == 0) {
        unsigned my = ldv(&g_gen);
        unsigned o = atomicAdd(&g_grp[(blockIdx.x & 7) * 32], 1u);
        if ((o & 15u) == 15u) {
            unsigned r = atomicAdd(&g_root, 1u);
            if ((r & 7u) == 7u) atomicAdd(&g_gen, 1u);
        }
        while (ldv(&g_gen) == my) { }
    }
    __syncthreads();
}

// 16-CTA group barrier (group = ks).
__device__ __forceinline__ void group_barrier(int g) {
    __threadfence();
    __syncthreads();
    if (threadIdx.x == 0) {
        unsigned my = ldv(&g_ggen[g * 32]);
        unsigned o = atomicAdd(&g_gcnt[g * 32], 1u);
        if ((o & 15u) == 15u) atomicAdd(&g_ggen[g * 32], 1u);
        while (ldv(&g_ggen[g * 32]) == my) { }
    }
    __syncthreads();
}

// ---------------------------------------------------------------------------
// Phase 1: x_proj via bf16 hi/lo mma.sync (unchanged from R12 — known good)
// ---------------------------------------------------------------------------
__global__ __launch_bounds__(256) void xproj_kernel(
    const float* __restrict__ X,
    const float* __restrict__ W_ih,
    const float* __restrict__ b_ih,
    const float* __restrict__ b_hh,
    float* __restrict__ hs)
{
    extern __shared__ char xsm[];
    const uint32_t sbase = smem_u32(xsm);
    const int nb = blockIdx.x;
    const int s  = blockIdx.y;
    const int tid = threadIdx.x;
    const int wid = tid >> 5;
    const int lid = tid & 31;

    const int wm = (wid & 3) * 32;
    const int wn = (wid >> 2) * 64;

    const uint32_t aRow = (uint32_t)(wm + (lid & 15));
    const uint32_t aCol = (uint32_t)((lid >> 4) * 8);
    const uint32_t aHiB = sbase + XA_HI + aRow * AST2 + aCol * 2;
    const uint32_t aLoB = aHiB + (XA_LO - XA_HI);
    const uint32_t bRow = (uint32_t)(wn + ((lid >> 4) << 3) + (lid & 7));
    const uint32_t bCol = (uint32_t)(((lid >> 3) & 1) * 8);
    const uint32_t bHiB = sbase + XB_HI + bRow * AST2 + bCol * 2;
    const uint32_t bLoB = bHiB + (XB_LO - XB_HI);

    float acc[2][8][4];
    #pragma unroll
    for (int mt = 0; mt < 2; mt++)
        #pragma unroll
        for (int nf = 0; nf < 8; nf++)
            #pragma unroll
            for (int r = 0; r < 4; r++) acc[mt][nf][r] = 0.0f;

    for (int c = 0; c < 4; c++) {
        const int kc = c * 64;
        #pragma unroll
        for (int i = 0; i < 8; i++) {
            int u = tid + i * 256;
            int m  = u >> 4;
            int c4 = u & 15;
            float4 v = *reinterpret_cast<const float4*>(
                X + ((size_t)m * Sdim + s) * Idim + kc + c4 * 4);
            uint2 uh, ul;
            split4(v, uh, ul);
            *reinterpret_cast<uint2*>(xsm + XA_HI + m * AST2 + c4 * 8) = uh;
            *reinterpret_cast<uint2*>(xsm + XA_LO + m * AST2 + c4 * 8) = ul;
        }
        #pragma unroll
        for (int i = 0; i < 8; i++) {
            int u = tid + i * 256;
            int n  = u >> 4;
            int c4 = u & 15;
            float4 v = *reinterpret_cast<const float4*>(
                W_ih + (size_t)(nb * 128 + n) * Idim + kc + c4 * 4);
            uint2 uh, ul;
            split4(v, uh, ul);
            *reinterpret_cast<uint2*>(xsm + XB_HI + n * AST2 + c4 * 8) = uh;
            *reinterpret_cast<uint2*>(xsm + XB_LO + n * AST2 + c4 * 8) = ul;
        }
        __syncthreads();

        #pragma unroll
        for (int kt = 0; kt < 4; kt++) {
            const uint32_t ko = (uint32_t)(kt * 32);
            uint32_t ah[2][4], al[2][4];
            LDSM4(ah[0], aHiB + ko);
            LDSM4(ah[1], aHiB + 16 * AST2 + ko);
            LDSM4(al[0], aLoB + ko);
            LDSM4(al[1], aLoB + 16 * AST2 + ko);
            #pragma unroll
            for (int np = 0; np < 4; np++) {
                uint32_t bh[4], bl[4];
                LDSM4(bh, bHiB + np * (16 * AST2) + ko);
                LDSM4(bl, bLoB + np * (16 * AST2) + ko);
                #pragma unroll
                for (int mt = 0; mt < 2; mt++) {
                    MMA_BF16(acc[mt][np * 2 + 0], ah[mt], bh + 0);
                    MMA_BF16(acc[mt][np * 2 + 0], ah[mt], bl + 0);
                    MMA_BF16(acc[mt][np * 2 + 0], al[mt], bh + 0);
                    MMA_BF16(acc[mt][np * 2 + 1], ah[mt], bh + 2);
                    MMA_BF16(acc[mt][np * 2 + 1], ah[mt], bl + 2);
                    MMA_BF16(acc[mt][np * 2 + 1], al[mt], bh + 2);
                }
            }
        }
        __syncthreads();
    }

    #pragma unroll
    for (int mt = 0; mt < 2; mt++) {
        const int row = wm + mt * 16 + (lid >> 2);
        #pragma unroll
        for (int nf = 0; nf < 8; nf++) {
            const int col = nb * 128 + wn + nf * 8 + (lid & 3) * 2;
            const float bb0 = __ldg(b_ih + col) + __ldg(b_hh + col);
            const float bb1 = __ldg(b_ih + col + 1) + __ldg(b_hh + col + 1);
            float* o = hs + ((size_t)s * Bdim + row) * Hdim + col;
            *reinterpret_cast<float2*>(o) =
                make_float2(acc[mt][nf][0] + bb0, acc[mt][nf][1] + bb1);
            *reinterpret_cast<float2*>(o + 8 * Hdim) =
                make_float2(acc[mt][nf][2] + bb0, acc[mt][nf][3] + bb1);
        }
    }
}

// ---------------------------------------------------------------------------
// Phase 2: persistent scan, 512 threads. CTA (nb, ks):
//   GEMM: A = staged tile gA[ks] (128 x 128), B = resident W_hh (64 x 128)
//   -> partials P[buf][ks][b][nb*64+..]
//   global barrier
//   reduce rows nb*8..+8 x cols ks*128..+128; tanh; write hs + staged gA[ks]
//   group barrier (16 CTAs of group ks)
// ---------------------------------------------------------------------------
__global__ __launch_bounds__(512, 1) void rnn_scan_kernel(
    const float* __restrict__ hidden,
    const float* __restrict__ W_hh,
    const float* __restrict__ W_fc,
    const float* __restrict__ b_fc,
    float* __restrict__ out,
    float* __restrict__ hs,
    float* __restrict__ ss,
    float* __restrict__ sf)
{
    extern __shared__ char smem[];
    const uint32_t sbase = smem_u32(smem);
    const int tid = threadIdx.x;
    const int wid = tid >> 5;
    const int lid = tid & 31;
    const int cta = blockIdx.x;
    const int nb  = cta >> 3;     // 0..15 N-block
    const int ks  = cta & 7;      // 0..7  K-split (= group id)
    const int k0  = ks * KBLK;

    // One-time: load + split W_hh tile [NBLK x KBLK] into resident padded smem
    #pragma unroll 4
    for (int i = 0; i < 16; i++) {
        int e = tid + i * 512;
        int n = e >> 7;
        int k = e & 127;
        float w = W_hh[(size_t)(nb * NBLK + n) * Hdim + k0 + k];
        __nv_bfloat16 hi = __float2bfloat16(w);
        __nv_bfloat16 lo = __float2bfloat16(w - __bfloat162float(hi));
        *reinterpret_cast<__nv_bfloat16*>(smem + SM_BHI + n * ASTRIDE + k * 2) = hi;
        *reinterpret_cast<__nv_bfloat16*>(smem + SM_BLO + n * ASTRIDE + k * 2) = lo;
    }

    // One-time: stage h0 rows nb*8..+8, cols k0..k0+127 into gA[ks]
    if (tid < 256) {
        int r = tid >> 5;                 // 0..7
        int c = (tid & 31) * 4;           // 0..124
        float4 v = *reinterpret_cast<const float4*>(
            hidden + (size_t)(nb * 8 + r) * Hdim + k0 + c);
        uint2 uh, ul;
        split4(v, uh, ul);
        size_t o = (size_t)ks * (Bdim * KBLK) + (size_t)(nb * 8 + r) * KBLK + c;
        *reinterpret_cast<uint2*>(g_Ahi + o) = uh;
        *reinterpret_cast<uint2*>(g_Alo + o) = ul;
    }
    __syncthreads();
    grid_barrier();   // h0 staged everywhere

    // warp layout: 4(m) x 4(n)
    const int wm = (wid & 3) * 32;   // 2 m-tiles of 16
    const int wn = (wid >> 2) * 16;  // 2 n-tiles of 8

    const uint32_t aRow = (uint32_t)(wm + (lid & 15));
    const uint32_t aCol = (uint32_t)((lid >> 4) * 8);
    const uint32_t aHiB = sbase + SM_AHI + aRow * ASTRIDE + aCol * 2;
    const uint32_t aLoB = aHiB + (SM_ALO - SM_AHI);
    const uint32_t bRow = (uint32_t)(wn + ((lid >> 4) << 3) + (lid & 7));
    const uint32_t bCol = (uint32_t)(((lid >> 3) & 1) * 8);
    const uint32_t bHiB = sbase + SM_BHI + bRow * ASTRIDE + bCol * 2;
    const uint32_t bLoB = bHiB + (SM_BLO - SM_BHI);

    const __nv_bfloat16* gAh = g_Ahi + (size_t)ks * (Bdim * KBLK);
    const __nv_bfloat16* gAl = g_Alo + (size_t)ks * (Bdim * KBLK);

    for (int t = 0; t < Sdim; t++) {
        float* Pbuf = g_P + (size_t)(t & 1) * (NK * Bdim * Hdim);

        // ---- A tile copy: gA[ks] (pre-split) -> padded smem ----
        #pragma unroll
        for (int i = 0; i < 4; i++) {
            int u = tid + i * 512;       // 0..2047 uint4 units
            int m  = u >> 4;             // 0..127
            int c8 = u & 15;             // 16B group
            uint4 vh = __ldcg(reinterpret_cast<const uint4*>(gAh) + u);
            uint4 vl = __ldcg(reinterpret_cast<const uint4*>(gAl) + u);
            *reinterpret_cast<uint4*>(smem + SM_AHI + m * ASTRIDE + c8 * 16) = vh;
            *reinterpret_cast<uint4*>(smem + SM_ALO + m * ASTRIDE + c8 * 16) = vl;
        }
        __syncthreads();

        // ---- ldmatrix + mma ----
        float acc[2][2][4];
        #pragma unroll
        for (int mt = 0; mt < 2; mt++)
            #pragma unroll
            for (int nt = 0; nt < 2; nt++)
                #pragma unroll
                for (int r = 0; r < 4; r++) acc[mt][nt][r] = 0.0f;

        #pragma unroll
        for (int kt = 0; kt < 8; kt++) {
            const uint32_t ko = (uint32_t)(kt * 32);
            uint32_t ah[2][4], al[2][4], bh[4], bl[4];
            LDSM4(ah[0], aHiB + ko);
            LDSM4(ah[1], aHiB + 16 * ASTRIDE + ko);
            LDSM4(al[0], aLoB + ko);
            LDSM4(al[1], aLoB + 16 * ASTRIDE + ko);
            LDSM4(bh, bHiB + ko);
            LDSM4(bl, bLoB + ko);
            #pragma unroll
            for (int mt = 0; mt < 2; mt++) {
                MMA_BF16(acc[mt][0], ah[mt], bh + 0);
                MMA_BF16(acc[mt][0], ah[mt], bl + 0);
                MMA_BF16(acc[mt][0], al[mt], bh + 0);
                MMA_BF16(acc[mt][1], ah[mt], bh + 2);
                MMA_BF16(acc[mt][1], ah[mt], bl + 2);
                MMA_BF16(acc[mt][1], al[mt], bh + 2);
            }
        }

        // ---- store partials ----
        #pragma unroll
        for (int mt = 0; mt < 2; mt++) {
            #pragma unroll
            for (int nt = 0; nt < 2; nt++) {
                const int row = wm + mt * 16 + (lid >> 2);
                const int col = wn + nt * 8 + (lid & 3) * 2;
                float* p = Pbuf + ((size_t)ks * Bdim + row) * Hdim + nb * NBLK + col;
                *reinterpret_cast<float2*>(p) =
                    make_float2(acc[mt][nt][0], acc[mt][nt][1]);
                *reinterpret_cast<float2*>(p + 8 * Hdim) =
                    make_float2(acc[mt][nt][2], acc[mt][nt][3]);
            }
        }

        grid_barrier();

        // ---- reduce rows nb*8..+8 x cols ks*128..+128 (1024 elems, float2/thread) ----
        {
            const int r = tid >> 6;                 // 0..7
            const int c = (tid & 63) * 2;           // 0..126
            const size_t row = (size_t)(nb * 8 + r);
            const size_t colH = (size_t)k0 + c;
            float* xp = hs + (size_t)t * Bdim * Hdim + row * Hdim + colH;
            float2 sum = *reinterpret_cast<const float2*>(xp);
            #pragma unroll
            for (int q = 0; q < NK; q++) {
                float2 p = ldcg2(Pbuf + ((size_t)q * Bdim + row) * Hdim + colH);
                sum.x += p.x; sum.y += p.y;
            }
            float2 hv = make_float2(tanh_fast(sum.x), tanh_fast(sum.y));
            *reinterpret_cast<float2*>(xp) = hv;

            uint32_t uh, ul;
            split2(hv, uh, ul);
            size_t o = (size_t)ks * (Bdim * KBLK) + row * KBLK + c;
            *reinterpret_cast<uint32_t*>(g_Ahi + o) = uh;
            *reinterpret_cast<uint32_t*>(g_Alo + o) = ul;
        }

        group_barrier(ks);
    }

    // ---- tail: state_start, state_final, fc output ----
    const float* hfin = hs + (size_t)(Sdim - 1) * Bdim * Hdim;
    {
        const size_t off = (size_t)cta * Hdim + tid * 2;
        *reinterpret_cast<float2*>(ss + off) = ldcg2(hs + off);
        *reinterpret_cast<float2*>(sf + off) = ldcg2(hfin + off);
    }
    if (cta < 8) {
        const int w = tid >> 5;       // 0..15
        const int lane = tid & 31;
        const int b = cta * 16 + w;   // 0..127
        float sum = 0.0f;
        #pragma unroll 8
        for (int h = lane; h < Hdim; h += 32)
            sum += __ldcg(hfin + (size_t)b * Hdim + h) * W_fc[h];
        #pragma unroll
        for (int o = 16; o > 0; o >>= 1)
            sum += __shfl_down_sync(0xffffffffu, sum, o);
        if (lane == 0) out[b] = sum + b_fc[0];
    }
}

extern "C" void kernel_launch(void* const* d_in, const int* in_sizes, int n_in,
                              void* d_out, int out_size) {
    (void)in_sizes; (void)n_in; (void)out_size;
    const float* X      = (const float*)d_in[0];
    const float* hidden = (const float*)d_in[1];
    const float* W_ih   = (const float*)d_in[2];
    const float* W_hh   = (const float*)d_in[3];
    const float* b_ih   = (const float*)d_in[4];
    const float* b_hh   = (const float*)d_in[5];
    const float* W_fc   = (const float*)d_in[6];
    const float* b_fc   = (const float*)d_in[7];

    float* out = (float*)d_out;                       // (B, 1)
    float* hs  = out + Bdim;                          // (S, B, H)
    float* ss  = hs + (size_t)Sdim * Bdim * Hdim;     // state_start (B,H)
    float* sf  = ss + (size_t)Bdim * Hdim;            // state_final (B,H)

    cudaFuncSetAttribute(xproj_kernel,
                         cudaFuncAttributeMaxDynamicSharedMemorySize, XSMEM_SZ);
    cudaFuncSetAttribute(rnn_scan_kernel,
                         cudaFuncAttributeMaxDynamicSharedMemorySize, SMEM_SZ);

    xproj_kernel<<<dim3(8, Sdim), 256, XSMEM_SZ>>>(X, W_ih, b_ih, b_hh, hs);
    rnn_scan_kernel<<<NCTA, 512, SMEM_SZ>>>(hidden, W_hh, W_fc, b_fc, out, hs, ss, sf);
}

// round 14
// speedup vs baseline: 2.1833x; 1.0824x over previous
#include <cuda_runtime.h>
#include <cuda_bf16.h>
#include <cstdint>
#include <cstddef>

#define Bdim 128
#define Sdim 512
#define Idim 256
#define Hdim 1024
#define NCTA 128

// scan decomposition: 16 N-blocks x 8 K-splits = 128 CTAs
#define NK 8
#define NBLK 64    // N columns per CTA (scan)
#define KBLK 128   // K slice per CTA (scan)

// A-fragment staging buffer geometry (uint32 units)
// frag id fi = (wr*8 + kt)*4 + prec*2 + mt ; per ks: 4*8*4 = 128 frags x 128 uints
#define AF_KS  (128 * 128)
#define AF_PAR (8 * AF_KS)

// xproj smem: K-chunk 64, padded 144 B stride
#define AST2 144
#define XA_HI 0
#define XA_LO (XA_HI + 128 * AST2)
#define XB_HI (XA_LO + 128 * AST2)
#define XB_LO (XB_HI + 128 * AST2)
#define XSMEM_SZ (XB_LO + 128 * AST2)     // 73728 B

__device__ float g_P[2 * NK * Bdim * Hdim];       // double-buffered split-K partials (8 MB)
__device__ uint32_t g_Af[2 * AF_PAR];             // fragment-layout staged A (hi/lo pairs), 1 MB
__device__ unsigned g_grp[8 * 32];                // init/final grid barrier tree
__device__ unsigned g_root = 0;
__device__ unsigned g_gen = 0;
__device__ unsigned g_gcnt[8 * 32];               // group barriers (per ks)
__device__ unsigned g_ggen[8 * 32];
__device__ unsigned g_done[8 * 32];               // per-ks gemm-done counters (monotonic)

// ---------------------------------------------------------------------------
// helpers
// ---------------------------------------------------------------------------
__device__ __forceinline__ unsigned ldv(const unsigned* p) {
    unsigned v;
    asm volatile("ld.volatile.global.u32 %0, [%1];" : "=r"(v) : "l"(p));
    return v;
}
__device__ __forceinline__ float2 ldcg2(const float* p) {
    return __ldcg(reinterpret_cast<const float2*>(p));
}
__device__ __forceinline__ float4 ldcg4(const float* p) {
    return __ldcg(reinterpret_cast<const float4*>(p));
}
__device__ __forceinline__ uint32_t smem_u32(const void* p) {
    uint32_t a;
    asm("{ .reg .u64 t; cvta.to.shared.u64 t, %1; cvt.u32.u64 %0, t; }" : "=r"(a) : "l"(p));
    return a;
}

#define LDSM4(r, addr) \
    asm volatile("ldmatrix.sync.aligned.m8n8.x4.shared.b16 {%0,%1,%2,%3}, [%4];" \
        : "=r"((r)[0]), "=r"((r)[1]), "=r"((r)[2]), "=r"((r)[3]) : "r"(addr))

#define MMA_BF16(d, a, b) \
    asm volatile("mma.sync.aligned.m16n8k16.row.col.f32.bf16.bf16.f32 " \
        "{%0,%1,%2,%3}, {%4,%5,%6,%7}, {%8,%9}, {%0,%1,%2,%3};" \
        : "+f"((d)[0]), "+f"((d)[1]), "+f"((d)[2]), "+f"((d)[3]) \
        : "r"((a)[0]), "r"((a)[1]), "r"((a)[2]), "r"((a)[3]), \
          "r"((b)[0]), "r"((b)[1]))

#define LDCG128(r, p) do { \
    uint4 v_ = __ldcg(reinterpret_cast<const uint4*>(p)); \
    (r)[0] = v_.x; (r)[1] = v_.y; (r)[2] = v_.z; (r)[3] = v_.w; } while (0)

__device__ __forceinline__ void split4(float4 v, uint2& uh, uint2& ul) {
    __nv_bfloat16 h0 = __float2bfloat16(v.x);
    __nv_bfloat16 h1 = __float2bfloat16(v.y);
    __nv_bfloat16 h2 = __float2bfloat16(v.z);
    __nv_bfloat16 h3 = __float2bfloat16(v.w);
    __nv_bfloat16 l0 = __float2bfloat16(v.x - __bfloat162float(h0));
    __nv_bfloat16 l1 = __float2bfloat16(v.y - __bfloat162float(h1));
    __nv_bfloat16 l2 = __float2bfloat16(v.z - __bfloat162float(h2));
    __nv_bfloat16 l3 = __float2bfloat16(v.w - __bfloat162float(h3));
    uh.x = (uint32_t)__bfloat16_as_ushort(h0) | ((uint32_t)__bfloat16_as_ushort(h1) << 16);
    uh.y = (uint32_t)__bfloat16_as_ushort(h2) | ((uint32_t)__bfloat16_as_ushort(h3) << 16);
    ul.x = (uint32_t)__bfloat16_as_ushort(l0) | ((uint32_t)__bfloat16_as_ushort(l1) << 16);
    ul.y = (uint32_t)__bfloat16_as_ushort(l2) | ((uint32_t)__bfloat16_as_ushort(l3) << 16);
}
__device__ __forceinline__ void split2(float2 v, uint32_t& uh, uint32_t& ul) {
    __nv_bfloat16 h0 = __float2bfloat16(v.x);
    __nv_bfloat16 h1 = __float2bfloat16(v.y);
    __nv_bfloat16 l0 = __float2bfloat16(v.x - __bfloat162float(h0));
    __nv_bfloat16 l1 = __float2bfloat16(v.y - __bfloat162float(h1));
    uh = (uint32_t)__bfloat16_as_ushort(h0) | ((uint32_t)__bfloat16_as_ushort(h1) << 16);
    ul = (uint32_t)__bfloat16_as_ushort(l0) | ((uint32_t)__bfloat16_as_ushort(l1) << 16);
}

__device__ __forceinline__ float tanh_fast(float x) {
    float xc = fminf(fmaxf(x, -9.0f), 9.0f);
    float e = __expf(2.0f * xc);
    return __fdividef(e - 1.0f, e + 1.0f);
}

// Full-grid two-level tree barrier (init/final only; monotonic, replay-safe).
__device__ __forceinline__ void grid_barrier() {
    __threadfence();
    __syncthreads();
    if (threadIdx.x == 0) {
        unsigned my = ldv(&g_gen);
        unsigned o = atomicAdd(&g_grp[(blockIdx.x & 7) * 32], 1u);
        if ((o & 15u) == 15u) {
            unsigned r = atomicAdd(&g_root, 1u);
            if ((r & 7u) == 7u) atomicAdd(&g_gen, 1u);
        }
        while (ldv(&g_gen) == my) { }
    }
    __syncthreads();
}

// 16-CTA group barrier (group = ks).
__device__ __forceinline__ void group_barrier(int g) {
    __threadfence();
    __syncthreads();
    if (threadIdx.x == 0) {
        unsigned my = ldv(&g_ggen[g * 32]);
        unsigned o = atomicAdd(&g_gcnt[g * 32], 1u);
        if ((o & 15u) == 15u) atomicAdd(&g_ggen[g * 32], 1u);
        while (ldv(&g_ggen[g * 32]) == my) { }
    }
    __syncthreads();
}

// Write one (hi, lo) column-pair of h into the fragment-layout staging buffer.
// Mirrors the mma.sync m16n8k16 A-fragment mapping:
//   reg p = (row8 ? 1 : 0) + (k8 ? 2 : 0), lane = (fr&7)*4 + ((fk&7)>>1)
__device__ __forceinline__ void stage_pair(int ks, int par, int row, int c,
                                           uint32_t uh, uint32_t ul) {
    int wr = row >> 5;
    int mt = (row >> 4) & 1;
    int fr = row & 15;
    int kt = c >> 4;
    int fk = c & 15;
    int p  = (fr >> 3) + ((fk >> 3) << 1);
    int lane = (fr & 7) * 4 + ((fk & 7) >> 1);
    int fiH = (wr * 8 + kt) * 4 + mt;        // prec 0
    uint32_t* b = g_Af + (size_t)par * AF_PAR + ks * AF_KS + lane * 4 + p;
    b[(size_t)fiH * 128]       = uh;
    b[(size_t)(fiH + 2) * 128] = ul;          // prec 1
}

// ---------------------------------------------------------------------------
// Phase 1: x_proj via bf16 hi/lo mma.sync (unchanged — known good)
// ---------------------------------------------------------------------------
__global__ __launch_bounds__(256) void xproj_kernel(
    const float* __restrict__ X,
    const float* __restrict__ W_ih,
    const float* __restrict__ b_ih,
    const float* __restrict__ b_hh,
    float* __restrict__ hs)
{
    extern __shared__ char xsm[];
    const uint32_t sbase = smem_u32(xsm);
    const int nb = blockIdx.x;
    const int s  = blockIdx.y;
    const int tid = threadIdx.x;
    const int wid = tid >> 5;
    const int lid = tid & 31;

    const int wm = (wid & 3) * 32;
    const int wn = (wid >> 2) * 64;

    const uint32_t aRow = (uint32_t)(wm + (lid & 15));
    const uint32_t aCol = (uint32_t)((lid >> 4) * 8);
    const uint32_t aHiB = sbase + XA_HI + aRow * AST2 + aCol * 2;
    const uint32_t aLoB = aHiB + (XA_LO - XA_HI);
    const uint32_t bRow = (uint32_t)(wn + ((lid >> 4) << 3) + (lid & 7));
    const uint32_t bCol = (uint32_t)(((lid >> 3) & 1) * 8);
    const uint32_t bHiB = sbase + XB_HI + bRow * AST2 + bCol * 2;
    const uint32_t bLoB = bHiB + (XB_LO - XB_HI);

    float acc[2][8][4];
    #pragma unroll
    for (int mt = 0; mt < 2; mt++)
        #pragma unroll
        for (int nf = 0; nf < 8; nf++)
            #pragma unroll
            for (int r = 0; r < 4; r++) acc[mt][nf][r] = 0.0f;

    for (int c = 0; c < 4; c++) {
        const int kc = c * 64;
        #pragma unroll
        for (int i = 0; i < 8; i++) {
            int u = tid + i * 256;
            int m  = u >> 4;
            int c4 = u & 15;
            float4 v = *reinterpret_cast<const float4*>(
                X + ((size_t)m * Sdim + s) * Idim + kc + c4 * 4);
            uint2 uh, ul;
            split4(v, uh, ul);
            *reinterpret_cast<uint2*>(xsm + XA_HI + m * AST2 + c4 * 8) = uh;
            *reinterpret_cast<uint2*>(xsm + XA_LO + m * AST2 + c4 * 8) = ul;
        }
        #pragma unroll
        for (int i = 0; i < 8; i++) {
            int u = tid + i * 256;
            int n  = u >> 4;
            int c4 = u & 15;
            float4 v = *reinterpret_cast<const float4*>(
                W_ih + (size_t)(nb * 128 + n) * Idim + kc + c4 * 4);
            uint2 uh, ul;
            split4(v, uh, ul);
            *reinterpret_cast<uint2*>(xsm + XB_HI + n * AST2 + c4 * 8) = uh;
            *reinterpret_cast<uint2*>(xsm + XB_LO + n * AST2 + c4 * 8) = ul;
        }
        __syncthreads();

        #pragma unroll
        for (int kt = 0; kt < 4; kt++) {
            const uint32_t ko = (uint32_t)(kt * 32);
            uint32_t ah[2][4], al[2][4];
            LDSM4(ah[0], aHiB + ko);
            LDSM4(ah[1], aHiB + 16 * AST2 + ko);
            LDSM4(al[0], aLoB + ko);
            LDSM4(al[1], aLoB + 16 * AST2 + ko);
            #pragma unroll
            for (int np = 0; np < 4; np++) {
                uint32_t bh[4], bl[4];
                LDSM4(bh, bHiB + np * (16 * AST2) + ko);
                LDSM4(bl, bLoB + np * (16 * AST2) + ko);
                #pragma unroll
                for (int mt = 0; mt < 2; mt++) {
                    MMA_BF16(acc[mt][np * 2 + 0], ah[mt], bh + 0);
                    MMA_BF16(acc[mt][np * 2 + 0], ah[mt], bl + 0);
                    MMA_BF16(acc[mt][np * 2 + 0], al[mt], bh + 0);
                    MMA_BF16(acc[mt][np * 2 + 1], ah[mt], bh + 2);
                    MMA_BF16(acc[mt][np * 2 + 1], ah[mt], bl + 2);
                    MMA_BF16(acc[mt][np * 2 + 1], al[mt], bh + 2);
                }
            }
        }
        __syncthreads();
    }

    #pragma unroll
    for (int mt = 0; mt < 2; mt++) {
        const int row = wm + mt * 16 + (lid >> 2);
        #pragma unroll
        for (int nf = 0; nf < 8; nf++) {
            const int col = nb * 128 + wn + nf * 8 + (lid & 3) * 2;
            const float bb0 = __ldg(b_ih + col) + __ldg(b_hh + col);
            const float bb1 = __ldg(b_ih + col + 1) + __ldg(b_hh + col + 1);
            float* o = hs + ((size_t)s * Bdim + row) * Hdim + col;
            *reinterpret_cast<float2*>(o) =
                make_float2(acc[mt][nf][0] + bb0, acc[mt][nf][1] + bb1);
            *reinterpret_cast<float2*>(o + 8 * Hdim) =
                make_float2(acc[mt][nf][2] + bb0, acc[mt][nf][3] + bb1);
        }
    }
}

// ---------------------------------------------------------------------------
// Phase 2: persistent scan, 256 threads, zero smem.
//  - B (W_hh tile) fragments hoisted into registers for all 512 steps.
//  - A fragments loaded straight from fragment-layout staged buffer (LDG.128).
//  - gemm -> fence -> signal done[nb>>1] ; reduce waits done[ks] ;
//    reduce -> stage h(t) fragments (parity (t+1)&1) -> group barrier(ks).
// ---------------------------------------------------------------------------
__global__ __launch_bounds__(256, 1) void rnn_scan_kernel(
    const float* __restrict__ hidden,
    const float* __restrict__ W_hh,
    const float* __restrict__ W_fc,
    const float* __restrict__ b_fc,
    float* __restrict__ out,
    float* __restrict__ hs,
    float* __restrict__ ss,
    float* __restrict__ sf)
{
    const int tid = threadIdx.x;
    const int wid = tid >> 5;
    const int lid = tid & 31;
    const int cta = blockIdx.x;
    const int nb  = cta >> 3;     // 0..15 N-block
    const int ks  = cta & 7;      // 0..7  K-split (= group id)
    const int k0  = ks * KBLK;

    // warp layout: 4(m) x 2(n)
    const int wr = wid & 3;          // m-row: rows wr*32..+31
    const int wm = wr * 32;
    const int wn = (wid >> 2) * 32;  // n-half: cols wn..wn+31 (of CTA's n64)

    // ---- one-time: hoist B (W_hh) fragments into registers (hi/lo) ----
    uint32_t bh[8][4][2], bl[8][4][2];
    #pragma unroll
    for (int kt = 0; kt < 8; kt++) {
        #pragma unroll
        for (int nt = 0; nt < 4; nt++) {
            int n_g = nb * NBLK + wn + nt * 8 + (lid >> 2);
            int k_g = k0 + kt * 16 + (lid & 3) * 2;
            const float* wp = W_hh + (size_t)n_g * Hdim + k_g;
            float2 w0 = *reinterpret_cast<const float2*>(wp);
            float2 w1 = *reinterpret_cast<const float2*>(wp + 8);
            split2(w0, bh[kt][nt][0], bl[kt][nt][0]);
            split2(w1, bh[kt][nt][1], bl[kt][nt][1]);
        }
    }

    // ---- one-time: stage h0 rows nb*8..+8 into gAf[ks] parity 0 ----
    #pragma unroll
    for (int e = 0; e < 2; e++) {
        int ph = tid * 2 + e;            // 0..511
        int rl = ph >> 6;                // 0..7
        int c  = (ph & 63) * 2;          // 0..126
        int row = nb * 8 + rl;
        float2 v = *reinterpret_cast<const float2*>(
            hidden + (size_t)row * Hdim + k0 + c);
        uint32_t uh, ul;
        split2(v, uh, ul);
        stage_pair(ks, 0, row, c, uh, ul);
    }

    // read done-counter base (before anyone signals), then align whole grid
    unsigned done_base = 0;
    if (tid == 0) done_base = ldv(&g_done[ks * 32]);
    grid_barrier();

    for (int t = 0; t < Sdim; t++) {
        float* Pbuf = g_P + (size_t)(t & 1) * (NK * Bdim * Hdim);
        const uint32_t* afb = g_Af + (size_t)(t & 1) * AF_PAR + ks * AF_KS + lid * 4;

        // ---- GEMM: A fragments via LDG.128, B from registers ----
        float acc[2][4][4];
        #pragma unroll
        for (int mt = 0; mt < 2; mt++)
            #pragma unroll
            for (int nt = 0; nt < 4; nt++)
                #pragma unroll
                for (int r = 0; r < 4; r++) acc[mt][nt][r] = 0.0f;

        uint32_t ah[2][2][4], al[2][2][4];   // [buf][mt][4]
        {
            const uint32_t* fb = afb + (size_t)(wr * 8 + 0) * 512;
            LDCG128(ah[0][0], fb);
            LDCG128(ah[0][1], fb + 128);
            LDCG128(al[0][0], fb + 256);
            LDCG128(al[0][1], fb + 384);
        }
        #pragma unroll
        for (int kt = 0; kt < 8; kt++) {
            const int cur = kt & 1, nxt = cur ^ 1;
            if (kt < 7) {
                const uint32_t* fb = afb + (size_t)(wr * 8 + kt + 1) * 512;
                LDCG128(ah[nxt][0], fb);
                LDCG128(ah[nxt][1], fb + 128);
                LDCG128(al[nxt][0], fb + 256);
                LDCG128(al[nxt][1], fb + 384);
            }
            #pragma unroll
            for (int mt = 0; mt < 2; mt++) {
                #pragma unroll
                for (int nt = 0; nt < 4; nt++) {
                    MMA_BF16(acc[mt][nt], ah[cur][mt], bh[kt][nt]);
                    MMA_BF16(acc[mt][nt], ah[cur][mt], bl[kt][nt]);
                    MMA_BF16(acc[mt][nt], al[cur][mt], bh[kt][nt]);
                }
            }
        }

        // ---- store partials ----
        #pragma unroll
        for (int mt = 0; mt < 2; mt++) {
            #pragma unroll
            for (int nt = 0; nt < 4; nt++) {
                const int row = wm + mt * 16 + (lid >> 2);
                const int col = wn + nt * 8 + (lid & 3) * 2;
                float* p = Pbuf + ((size_t)ks * Bdim + row) * Hdim + nb * NBLK + col;
                *reinterpret_cast<float2*>(p) =
                    make_float2(acc[mt][nt][0], acc[mt][nt][1]);
                *reinterpret_cast<float2*>(p + 8 * Hdim) =
                    make_float2(acc[mt][nt][2], acc[mt][nt][3]);
            }
        }

        // ---- signal gemm done for column-group nb>>1 ----
        __threadfence();
        __syncthreads();
        if (tid == 0) {
            atomicAdd(&g_done[(nb >> 1) * 32], 1u);
            // wait for the 16 producers of our reduce slice
            while (ldv(&g_done[ks * 32]) - done_base < 16u * (unsigned)(t + 1)) { }
        }
        __syncthreads();

        // ---- reduce rows nb*8..+8 x cols ks*128..+128; tanh; stage h(t) ----
        {
            const int par = (t + 1) & 1;
            #pragma unroll
            for (int e = 0; e < 2; e++) {
                int ph = tid * 2 + e;
                int rl = ph >> 6;
                int c  = (ph & 63) * 2;
                int row = nb * 8 + rl;
                const size_t colH = (size_t)k0 + c;
                float* xp = hs + (size_t)t * Bdim * Hdim + (size_t)row * Hdim + colH;
                float2 sum = *reinterpret_cast<const float2*>(xp);
                #pragma unroll
                for (int q = 0; q < NK; q++) {
                    float2 pv = ldcg2(Pbuf + ((size_t)q * Bdim + row) * Hdim + colH);
                    sum.x += pv.x; sum.y += pv.y;
                }
                float2 hv = make_float2(tanh_fast(sum.x), tanh_fast(sum.y));
                *reinterpret_cast<float2*>(xp) = hv;
                uint32_t uh, ul;
                split2(hv, uh, ul);
                stage_pair(ks, par, row, c, uh, ul);
            }
        }

        group_barrier(ks);
    }

    grid_barrier();   // all hs rows final before cross-row tail reads

    // ---- tail: state_start, state_final, fc output ----
    const float* hfin = hs + (size_t)(Sdim - 1) * Bdim * Hdim;
    {
        const size_t off = (size_t)cta * Hdim + tid * 4;
        *reinterpret_cast<float4*>(ss + off) = ldcg4(hs + off);
        *reinterpret_cast<float4*>(sf + off) = ldcg4(hfin + off);
    }
    if (cta < 16) {
        const int w = tid >> 5;
        const int lane = tid & 31;
        const int b = cta * 8 + w;
        float sum = 0.0f;
        #pragma unroll 8
        for (int h = lane; h < Hdim; h += 32)
            sum += __ldcg(hfin + (size_t)b * Hdim + h) * W_fc[h];
        #pragma unroll
        for (int o = 16; o > 0; o >>= 1)
            sum += __shfl_down_sync(0xffffffffu, sum, o);
        if (lane == 0) out[b] = sum + b_fc[0];
    }
}

extern "C" void kernel_launch(void* const* d_in, const int* in_sizes, int n_in,
                              void* d_out, int out_size) {
    (void)in_sizes; (void)n_in; (void)out_size;
    const float* X      = (const float*)d_in[0];
    const float* hidden = (const float*)d_in[1];
    const float* W_ih   = (const float*)d_in[2];
    const float* W_hh   = (const float*)d_in[3];
    const float* b_ih   = (const float*)d_in[4];
    const float* b_hh   = (const float*)d_in[5];
    const float* W_fc   = (const float*)d_in[6];
    const float* b_fc   = (const float*)d_in[7];

    float* out = (float*)d_out;                       // (B, 1)
    float* hs  = out + Bdim;                          // (S, B, H)
    float* ss  = hs + (size_t)Sdim * Bdim * Hdim;     // state_start (B,H)
    float* sf  = ss + (size_t)Bdim * Hdim;            // state_final (B,H)

    cudaFuncSetAttribute(xproj_kernel,
                         cudaFuncAttributeMaxDynamicSharedMemorySize, XSMEM_SZ);

    xproj_kernel<<<dim3(8, Sdim), 256, XSMEM_SZ>>>(X, W_ih, b_ih, b_hh, hs);
    rnn_scan_kernel<<<NCTA, 256>>>(hidden, W_hh, W_fc, b_fc, out, hs, ss, sf);
}